// round 14
// baseline (speedup 1.0000x reference)
#include <cuda_runtime.h>

#define NVOX   400000
#define K27    27
#define VB     8
#define NBATCH (NVOX / VB)                 // 50000 exact
#define NWARP  16
#define NTHR   (NWARP * 32)
#define WQ_FLOATS (K27 * 1024)             // 27648 floats = 110,592 B
#define RING_F 512                         // 8 rows * 64 floats
#define QUE_F  224                         // 216 max entries (+pad)
#define ACC_F  1024                        // 8 v * 32 lanes * ulonglong2
#define WARP_F (RING_F + QUE_F + ACC_F)    // 1760 floats = 7040 B
#define SMEM_BYTES ((WQ_FLOATS + NWARP * WARP_F) * 4)   // 223,232 B

typedef unsigned long long u64;

#define CP16(dst, src) \
    asm volatile("cp.async.cg.shared.global [%0], [%1], 16;\n" :: "r"(dst), "l"(src))
#define CPCOMMIT() asm volatile("cp.async.commit_group;\n" ::: "memory")
#define CPWAIT(n)  asm volatile("cp.async.wait_group %0;\n" :: "n"(n) : "memory")
#define FMA2(acc, a, b) asm("fma.rn.f32x2 %0, %1, %2, %0;" : "+l"(acc) : "l"(a), "l"(b))
#define ADD2(d, a, b)   asm("add.rn.f32x2 %0, %1, %2;" : "=l"(d) : "l"(a), "l"(b))
__device__ __forceinline__ void upk2(float& lo, float& hi, u64 p) {
    asm("mov.b64 {%0, %1}, %2;" : "=f"(lo), "=f"(hi) : "l"(p));
}

__global__ void __launch_bounds__(NTHR, 1)
subm_conv_kernel(const float* __restrict__ feat,
                 const float* __restrict__ wgt,
                 const float* __restrict__ bias,
                 const int*   __restrict__ nbr,
                 float*       __restrict__ out)
{
    extern __shared__ float smem[];
    const int tid = threadIdx.x, lane = tid & 31, warp = tid >> 5;
    const unsigned FULL = 0xffffffffu;

    float*      wbase = smem + WQ_FLOATS + warp * WARP_F;
    float*      ring  = wbase;                               // 8 rows x 256 B
    int*        que   = (int*)(wbase + RING_F);              // packed entries
    ulonglong2* acc   = (ulonglong2*)(wbase + RING_F + QUE_F);

    // Weight fill. src t = ((g*27+k)*16+ci)*16+co (co fastest == linear t).
    // dst float4 (k, j=ci>>1, g*8+(co>>1)) = {w[2j][c0],w[2j+1][c0],w[2j][c1],w[2j+1][c1]}
    for (int t = tid; t < 108 * 256; t += NTHR) {
        int co = t & 15, ci = (t >> 4) & 15, gk = t >> 8;
        int gg = gk / K27, kk = gk % K27;
        int j = ci >> 1, par = ci & 1, rr = co >> 1, ce = co & 1;
        smem[(((kk * 8 + j) * 32) + (gg * 8 + rr)) * 4 + ce * 2 + par] = wgt[t];
    }
    __syncthreads();

    const int g = lane >> 3, r = lane & 7;
    const float b0 = bias[g * 16 + 2 * r];
    const float b1 = bias[g * 16 + 2 * r + 1];
    const unsigned ring_u32 = (unsigned)__cvta_generic_to_shared(ring);
    const int bstride = gridDim.x * NWARP;

    for (int batch = blockIdx.x * NWARP + warp; batch < NBATCH; batch += bstride) {
        const int vb = batch * VB;

        // ---- build k-major compacted queue: entry = (idx<<9)|(k<<4)|v
        unsigned vbits = 0;
        int myidx[VB];
        if (lane < K27) {
#pragma unroll
            for (int v = 0; v < VB; ++v) {
                int ii = nbr[(vb + v) * K27 + lane];
                myidx[v] = ii;
                vbits |= (unsigned)(ii >= 0) << v;
            }
        }
        const int cnt = __popc(vbits);
        int inc = cnt;
#pragma unroll
        for (int d = 1; d < 32; d <<= 1) {
            int t2 = __shfl_up_sync(FULL, inc, d);
            if (lane >= d) inc += t2;
        }
        int ofs = inc - cnt;
        const int total = __shfl_sync(FULL, inc, 31);   // >= VB (center k always valid)
#pragma unroll
        for (int v = 0; v < VB; ++v)
            if (vbits & (1u << v)) que[ofs++] = (myidx[v] << 9) | (lane << 4) | v;

#pragma unroll
        for (int v = 0; v < VB; ++v)
            acc[(v << 5) + lane] = make_ulonglong2(0ull, 0ull);
        __syncwarp();

        // ---- producer: groups of 4 rows, all 32 lanes (2 rows per CP16 pass)
        int pe = 0;
        auto produce4 = [&]() {
#pragma unroll
            for (int h = 0; h < 2; ++h) {
                const int rrow = pe + 2 * h + (lane >> 4);
                const int qi = min(rrow, total - 1);
                const int ent = que[qi];
                if (rrow < total)
                    CP16(ring_u32 + (((rrow & 7) << 8) + ((lane & 15) << 4)),
                         feat + (long long)(ent >> 9) * 64 + (lane & 15) * 4);
            }
            pe += 4;
            CPCOMMIT();
        };
        produce4(); produce4();          // 8 rows in flight

        int kcur = -1;
        ulonglong2 W0, W1, W2, W3, W4, W5, W6, W7;

        for (int e = 0; e < total; e += 4) {
            CPWAIT(1);
            __syncwarp();

            u64 q0[4], q1[4];
            int vv[4];
            // phase 1: 4 independent fresh-register FMA2 chains
#pragma unroll
            for (int u = 0; u < 4; ++u) {
                q0[u] = 0ull; q1[u] = 0ull; vv[u] = -1;
                if (e + u < total) {
                    const int ent = que[e + u];
                    vv[u] = ent & 15;
                    const int k = (ent >> 4) & 31;
                    if (k != kcur) {                   // uniform branch
                        kcur = k;
                        const ulonglong2* wp = (const ulonglong2*)(smem + (k << 10)) + lane;
                        W0 = wp[0];   W1 = wp[32];  W2 = wp[64];  W3 = wp[96];
                        W4 = wp[128]; W5 = wp[160]; W6 = wp[192]; W7 = wp[224];
                    }
                    const ulonglong2* ap =
                        (const ulonglong2*)(ring + (((e + u) & 7) << 6) + (g << 4));
                    const ulonglong2 A0 = ap[0], A1 = ap[1], A2 = ap[2], A3 = ap[3];
                    u64 p0 = 0ull, p1 = 0ull;
                    FMA2(p0, A0.x, W0.x); FMA2(p1, A0.x, W0.y);
                    FMA2(p0, A0.y, W1.x); FMA2(p1, A0.y, W1.y);
                    FMA2(p0, A1.x, W2.x); FMA2(p1, A1.x, W2.y);
                    FMA2(p0, A1.y, W3.x); FMA2(p1, A1.y, W3.y);
                    FMA2(p0, A2.x, W4.x); FMA2(p1, A2.x, W4.y);
                    FMA2(p0, A2.y, W5.x); FMA2(p1, A2.y, W5.y);
                    FMA2(p0, A3.x, W6.x); FMA2(p1, A3.x, W6.y);
                    FMA2(p0, A3.y, W7.x); FMA2(p1, A3.y, W7.y);
                    q0[u] = p0; q1[u] = p1;
                }
            }
            // phase 2: short read-add-write merge into smem accumulators
#pragma unroll
            for (int u = 0; u < 4; ++u)
                if (vv[u] >= 0) {
                    ulonglong2 P = acc[(vv[u] << 5) + lane];
                    ADD2(P.x, P.x, q0[u]);
                    ADD2(P.y, P.y, q1[u]);
                    acc[(vv[u] << 5) + lane] = P;
                }

            produce4();
        }
        CPWAIT(0);
        __syncwarp();

        // ---- epilogue: fold even/odd ci halves, add bias, contiguous stores
#pragma unroll
        for (int v = 0; v < VB; ++v) {
            const ulonglong2 P = acc[(v << 5) + lane];
            float e0, o0, e1, o1;
            upk2(e0, o0, P.x);
            upk2(e1, o1, P.y);
            *(float2*)(out + (long long)(vb + v) * 64 + g * 16 + 2 * r) =
                make_float2(e0 + o0 + b0, e1 + o1 + b1);
        }
    }
}

extern "C" void kernel_launch(void* const* d_in, const int* in_sizes, int n_in,
                              void* d_out, int out_size) {
    const float* feat = (const float*)d_in[0];
    const float* wgt  = (const float*)d_in[1];
    const float* bias = (const float*)d_in[2];
    const int*   nbr  = (const int*)d_in[3];
    float* out = (float*)d_out;

    cudaFuncSetAttribute(subm_conv_kernel,
                         cudaFuncAttributeMaxDynamicSharedMemorySize, SMEM_BYTES);
    subm_conv_kernel<<<148, NTHR, SMEM_BYTES>>>(feat, wgt, bias, nbr, out);
}

// round 15
// speedup vs baseline: 1.7401x; 1.7401x over previous
#include <cuda_runtime.h>

#define NVOX   400000
#define K27    27
#define VB     10
#define NBATCH (NVOX / VB)                 // 40000 exact
#define NWARP  16
#define NTHR   (NWARP * 32)
#define WQ_FLOATS (K27 * 1024)             // 27648 floats = 110,592 B
#define RING_F 512                         // 8 rows * 64 floats
#define QUE_F  272                         // 270 max entries (+pad)
#define WARP_F (RING_F + QUE_F)            // 784 floats = 3136 B
#define SMEM_BYTES ((WQ_FLOATS + NWARP * WARP_F) * 4)   // 160,768 B

typedef unsigned long long u64;

#define CP16(dst, src) \
    asm volatile("cp.async.cg.shared.global [%0], [%1], 16;\n" :: "r"(dst), "l"(src))
#define CPCOMMIT() asm volatile("cp.async.commit_group;\n" ::: "memory")
#define CPWAIT(n)  asm volatile("cp.async.wait_group %0;\n" :: "n"(n) : "memory")
#define FMA2(acc, a, b) asm("fma.rn.f32x2 %0, %1, %2, %0;" : "+l"(acc) : "l"(a), "l"(b))
#define ADD2(d, a, b)   asm("add.rn.f32x2 %0, %1, %2;" : "=l"(d) : "l"(a), "l"(b))
__device__ __forceinline__ void upk2(float& lo, float& hi, u64 p) {
    asm("mov.b64 {%0, %1}, %2;" : "=f"(lo), "=f"(hi) : "l"(p));
}

// uniform-v merge arm
#define MERGE(vn) { ADD2(acc0[vn], acc0[vn], p0); ADD2(acc1[vn], acc1[vn], p1); }

__global__ void __launch_bounds__(NTHR, 1)
subm_conv_kernel(const float* __restrict__ feat,
                 const float* __restrict__ wgt,
                 const float* __restrict__ bias,
                 const int*   __restrict__ nbr,
                 float*       __restrict__ out)
{
    extern __shared__ float smem[];
    const int tid = threadIdx.x, lane = tid & 31, warp = tid >> 5;
    const unsigned FULL = 0xffffffffu;

    float* wbase = smem + WQ_FLOATS + warp * WARP_F;
    float* ring  = wbase;                          // 8 rows x 256 B
    int*   que   = (int*)(wbase + RING_F);         // packed entries, k-major

    // Weight fill. src t = ((g*27+k)*16+ci)*16+co (co fastest == linear t).
    // dst float4 (k, j=ci>>1, g*8+(co>>1)) = {w[2j][c0],w[2j+1][c0],w[2j][c1],w[2j+1][c1]}
    for (int t = tid; t < 108 * 256; t += NTHR) {
        int co = t & 15, ci = (t >> 4) & 15, gk = t >> 8;
        int gg = gk / K27, kk = gk % K27;
        int j = ci >> 1, par = ci & 1, rr = co >> 1, ce = co & 1;
        smem[(((kk * 8 + j) * 32) + (gg * 8 + rr)) * 4 + ce * 2 + par] = wgt[t];
    }
    __syncthreads();

    const int g = lane >> 3, r = lane & 7;
    const float b0 = bias[g * 16 + 2 * r];
    const float b1 = bias[g * 16 + 2 * r + 1];
    const unsigned ring_u32 = (unsigned)__cvta_generic_to_shared(ring);
    const int bstride = gridDim.x * NWARP;

    for (int batch = blockIdx.x * NWARP + warp; batch < NBATCH; batch += bstride) {
        const int vb = batch * VB;

        // ---- build k-major compacted queue: entry = (idx<<9)|(k<<4)|v
        unsigned vbits = 0;
        int myidx[VB];
        if (lane < K27) {
#pragma unroll
            for (int v = 0; v < VB; ++v) {
                int ii = nbr[(vb + v) * K27 + lane];
                myidx[v] = ii;
                vbits |= (unsigned)(ii >= 0) << v;
            }
        }
        const int cnt = __popc(vbits);
        int inc = cnt;
#pragma unroll
        for (int d = 1; d < 32; d <<= 1) {
            int t2 = __shfl_up_sync(FULL, inc, d);
            if (lane >= d) inc += t2;
        }
        int ofs = inc - cnt;
        const int total = __shfl_sync(FULL, inc, 31);   // >= VB (center k valid)
#pragma unroll
        for (int v = 0; v < VB; ++v)
            if (vbits & (1u << v)) que[ofs++] = (myidx[v] << 9) | (lane << 4) | v;
        __syncwarp();

        // ---- producer: groups of 4 rows, all 32 lanes (2 rows per pass)
        int pe = 0;
        auto produce4 = [&]() {
#pragma unroll
            for (int h = 0; h < 2; ++h) {
                const int rrow = pe + 2 * h + (lane >> 4);
                const int ent = que[min(rrow, total - 1)];
                if (rrow < total)
                    CP16(ring_u32 + (((rrow & 7) << 8) + ((lane & 15) << 4)),
                         feat + (long long)(ent >> 9) * 64 + (lane & 15) * 4);
            }
            pe += 4;
            CPCOMMIT();
        };
        produce4(); produce4();          // 8 rows in flight

        u64 acc0[VB], acc1[VB];
#pragma unroll
        for (int v = 0; v < VB; ++v) { acc0[v] = 0ull; acc1[v] = 0ull; }

        int kcur = -1;
        ulonglong2 W0, W1, W2, W3, W4, W5, W6, W7;

        for (int e = 0; e < total; e += 4) {
            CPWAIT(1);
            __syncwarp();

#pragma unroll
            for (int u = 0; u < 4; ++u) {
                if (e + u < total) {                   // uniform
                    const int ent = que[e + u];
                    const int k = (ent >> 4) & 31;
                    if (k != kcur) {                   // uniform, ~0.37/entry
                        kcur = k;
                        const ulonglong2* wp = (const ulonglong2*)(smem + (k << 10)) + lane;
                        W0 = wp[0];   W1 = wp[32];  W2 = wp[64];  W3 = wp[96];
                        W4 = wp[128]; W5 = wp[160]; W6 = wp[192]; W7 = wp[224];
                    }
                    // fresh-register partial: unconditional dense FMA2 chain
                    const ulonglong2* ap =
                        (const ulonglong2*)(ring + (((e + u) & 7) << 6) + (g << 4));
                    const ulonglong2 A0 = ap[0], A1 = ap[1];
                    u64 p0 = 0ull, p1 = 0ull;
                    FMA2(p0, A0.x, W0.x); FMA2(p1, A0.x, W0.y);
                    FMA2(p0, A0.y, W1.x); FMA2(p1, A0.y, W1.y);
                    FMA2(p0, A1.x, W2.x); FMA2(p1, A1.x, W2.y);
                    FMA2(p0, A1.y, W3.x); FMA2(p1, A1.y, W3.y);
                    const ulonglong2 A2 = ap[2], A3 = ap[3];
                    FMA2(p0, A2.x, W4.x); FMA2(p1, A2.x, W4.y);
                    FMA2(p0, A2.y, W5.x); FMA2(p1, A2.y, W5.y);
                    FMA2(p0, A3.x, W6.x); FMA2(p1, A3.x, W6.y);
                    FMA2(p0, A3.y, W7.x); FMA2(p1, A3.y, W7.y);

                    // v is WARP-UNIFORM -> cheap uniform branch chain, no
                    // divergence, register-direct accumulation.
                    const int v = ent & 15;
                    if      (v == 0) MERGE(0)
                    else if (v == 1) MERGE(1)
                    else if (v == 2) MERGE(2)
                    else if (v == 3) MERGE(3)
                    else if (v == 4) MERGE(4)
                    else if (v == 5) MERGE(5)
                    else if (v == 6) MERGE(6)
                    else if (v == 7) MERGE(7)
                    else if (v == 8) MERGE(8)
                    else             MERGE(9)
                }
            }
            produce4();
        }
        CPWAIT(0);
        __syncwarp();

        // ---- epilogue: fold even/odd ci halves, add bias, contiguous stores
#pragma unroll
        for (int v = 0; v < VB; ++v) {
            float e0, o0, e1, o1;
            upk2(e0, o0, acc0[v]);
            upk2(e1, o1, acc1[v]);
            *(float2*)(out + (long long)(vb + v) * 64 + g * 16 + 2 * r) =
                make_float2(e0 + o0 + b0, e1 + o1 + b1);
        }
    }
}

extern "C" void kernel_launch(void* const* d_in, const int* in_sizes, int n_in,
                              void* d_out, int out_size) {
    const float* feat = (const float*)d_in[0];
    const float* wgt  = (const float*)d_in[1];
    const float* bias = (const float*)d_in[2];
    const int*   nbr  = (const int*)d_in[3];
    float* out = (float*)d_out;

    cudaFuncSetAttribute(subm_conv_kernel,
                         cudaFuncAttributeMaxDynamicSharedMemorySize, SMEM_BYTES);
    subm_conv_kernel<<<148, NTHR, SMEM_BYTES>>>(feat, wgt, bias, nbr, out);
}

// round 16
// speedup vs baseline: 1.8987x; 1.0911x over previous
#include <cuda_runtime.h>

#define NVOX   400000
#define K27    27
#define VB     10
#define NBATCH (NVOX / VB)                 // 40000 exact
#define NWARP  16
#define NTHR   (NWARP * 32)
#define WQ_FLOATS (K27 * 1024)             // 27648 floats = 110,592 B
#define RING_F 1024                        // 16 rows * 64 floats
#define QUE_F  288                         // 270 max entries (+pad, 16B aligned)
#define WARP_F (RING_F + QUE_F)            // 1312 floats = 5248 B
#define SMEM_BYTES ((WQ_FLOATS + NWARP * WARP_F) * 4)   // 194,560 B

typedef unsigned long long u64;

#define CP16(dst, src) \
    asm volatile("cp.async.cg.shared.global [%0], [%1], 16;\n" :: "r"(dst), "l"(src))
#define CPCOMMIT() asm volatile("cp.async.commit_group;\n" ::: "memory")
#define CPWAIT(n)  asm volatile("cp.async.wait_group %0;\n" :: "n"(n) : "memory")
#define FMA2(acc, a, b) asm("fma.rn.f32x2 %0, %1, %2, %0;" : "+l"(acc) : "l"(a), "l"(b))
#define ADD2(d, a, b)   asm("add.rn.f32x2 %0, %1, %2;" : "=l"(d) : "l"(a), "l"(b))
__device__ __forceinline__ void upk2(float& lo, float& hi, u64 p) {
    asm("mov.b64 {%0, %1}, %2;" : "=f"(lo), "=f"(hi) : "l"(p));
}

#define MERGE(vn) { ADD2(acc0[vn], acc0[vn], p0); ADD2(acc1[vn], acc1[vn], p1); }

__global__ void __launch_bounds__(NTHR, 1)
subm_conv_kernel(const float* __restrict__ feat,
                 const float* __restrict__ wgt,
                 const float* __restrict__ bias,
                 const int*   __restrict__ nbr,
                 float*       __restrict__ out)
{
    extern __shared__ float smem[];
    const int tid = threadIdx.x, lane = tid & 31, warp = tid >> 5;
    const unsigned FULL = 0xffffffffu;

    float* wbase = smem + WQ_FLOATS + warp * WARP_F;
    float* ring  = wbase;                          // 16 rows x 256 B
    int*   que   = (int*)(wbase + RING_F);         // packed entries, k-major

    // Weight fill. src t = ((g*27+k)*16+ci)*16+co (co fastest == linear t).
    // dst float4 (k, j=ci>>1, g*8+(co>>1)) = {w[2j][c0],w[2j+1][c0],w[2j][c1],w[2j+1][c1]}
    for (int t = tid; t < 108 * 256; t += NTHR) {
        int co = t & 15, ci = (t >> 4) & 15, gk = t >> 8;
        int gg = gk / K27, kk = gk % K27;
        int j = ci >> 1, par = ci & 1, rr = co >> 1, ce = co & 1;
        smem[(((kk * 8 + j) * 32) + (gg * 8 + rr)) * 4 + ce * 2 + par] = wgt[t];
    }
    __syncthreads();

    const int g = lane >> 3, r = lane & 7;
    const float b0 = bias[g * 16 + 2 * r];
    const float b1 = bias[g * 16 + 2 * r + 1];
    const unsigned ring_u32 = (unsigned)__cvta_generic_to_shared(ring);
    const int bstride = gridDim.x * NWARP;

    for (int batch = blockIdx.x * NWARP + warp; batch < NBATCH; batch += bstride) {
        const int vb = batch * VB;

        // ---- build k-major compacted queue: entry = (idx<<9)|(k<<4)|v
        unsigned vbits = 0;
        int myidx[VB];
        if (lane < K27) {
#pragma unroll
            for (int v = 0; v < VB; ++v) {
                int ii = nbr[(vb + v) * K27 + lane];
                myidx[v] = ii;
                vbits |= (unsigned)(ii >= 0) << v;
            }
        }
        const int cnt = __popc(vbits);
        int inc = cnt;
#pragma unroll
        for (int d = 1; d < 32; d <<= 1) {
            int t2 = __shfl_up_sync(FULL, inc, d);
            if (lane >= d) inc += t2;
        }
        int ofs = inc - cnt;
        const int total = __shfl_sync(FULL, inc, 31);   // >= VB (center k valid)
#pragma unroll
        for (int v = 0; v < VB; ++v)
            if (vbits & (1u << v)) que[ofs++] = (myidx[v] << 9) | (lane << 4) | v;
        __syncwarp();

        // ---- producer: groups of 4 rows, all 32 lanes (2 rows per pass)
        int pe = 0;
        auto produce4 = [&]() {
#pragma unroll
            for (int h = 0; h < 2; ++h) {
                const int rrow = pe + 2 * h + (lane >> 4);
                const int ent = que[min(rrow, total - 1)];
                if (rrow < total)
                    CP16(ring_u32 + (((rrow & 15) << 8) + ((lane & 15) << 4)),
                         feat + (long long)(ent >> 9) * 64 + (lane & 15) * 4);
            }
            pe += 4;
            CPCOMMIT();
        };
        produce4(); produce4(); produce4(); produce4();   // 16 rows / 4 groups deep

        u64 acc0[VB], acc1[VB];
#pragma unroll
        for (int v = 0; v < VB; ++v) { acc0[v] = 0ull; acc1[v] = 0ull; }

        int kcur = -1;
        ulonglong2 W0, W1, W2, W3, W4, W5, W6, W7;

        for (int e = 0; e < total; e += 4) {
            CPWAIT(3);                 // group for rows e..e+3 complete
            __syncwarp();

            const int4 qe = *(const int4*)(que + e);   // 1 LDS.128 for 4 entries
#pragma unroll
            for (int u = 0; u < 4; ++u) {
                if (e + u < total) {                   // uniform
                    const int ent = (u == 0) ? qe.x : (u == 1) ? qe.y
                                  : (u == 2) ? qe.z : qe.w;
                    const int k = (ent >> 4) & 31;
                    if (k != kcur) {                   // uniform, ~0.4/entry
                        kcur = k;
                        const ulonglong2* wp = (const ulonglong2*)(smem + (k << 10)) + lane;
                        W0 = wp[0];   W1 = wp[32];  W2 = wp[64];  W3 = wp[96];
                        W4 = wp[128]; W5 = wp[160]; W6 = wp[192]; W7 = wp[224];
                    }
                    // fresh-register partial: unconditional dense FMA2 chain
                    const ulonglong2* ap =
                        (const ulonglong2*)(ring + (((e + u) & 15) << 6) + (g << 4));
                    const ulonglong2 A0 = ap[0], A1 = ap[1];
                    u64 p0 = 0ull, p1 = 0ull;
                    FMA2(p0, A0.x, W0.x); FMA2(p1, A0.x, W0.y);
                    FMA2(p0, A0.y, W1.x); FMA2(p1, A0.y, W1.y);
                    FMA2(p0, A1.x, W2.x); FMA2(p1, A1.x, W2.y);
                    FMA2(p0, A1.y, W3.x); FMA2(p1, A1.y, W3.y);
                    const ulonglong2 A2 = ap[2], A3 = ap[3];
                    FMA2(p0, A2.x, W4.x); FMA2(p1, A2.x, W4.y);
                    FMA2(p0, A2.y, W5.x); FMA2(p1, A2.y, W5.y);
                    FMA2(p0, A3.x, W6.x); FMA2(p1, A3.x, W6.y);
                    FMA2(p0, A3.y, W7.x); FMA2(p1, A3.y, W7.y);

                    // v warp-uniform -> 3-compare binary tree, register acc
                    const int v = ent & 15;
                    if (v < 4) {
                        if (v < 2) { if (v == 0) MERGE(0) else MERGE(1) }
                        else       { if (v == 2) MERGE(2) else MERGE(3) }
                    } else if (v < 8) {
                        if (v < 6) { if (v == 4) MERGE(4) else MERGE(5) }
                        else       { if (v == 6) MERGE(6) else MERGE(7) }
                    } else {
                        if (v == 8) MERGE(8) else MERGE(9)
                    }
                }
            }
            produce4();                // rows e+16..e+19 -> slots just freed
        }
        CPWAIT(0);
        __syncwarp();

        // ---- epilogue: fold even/odd ci halves, add bias, contiguous stores
#pragma unroll
        for (int v = 0; v < VB; ++v) {
            float e0, o0, e1, o1;
            upk2(e0, o0, acc0[v]);
            upk2(e1, o1, acc1[v]);
            *(float2*)(out + (long long)(vb + v) * 64 + g * 16 + 2 * r) =
                make_float2(e0 + o0 + b0, e1 + o1 + b1);
        }
    }
}

extern "C" void kernel_launch(void* const* d_in, const int* in_sizes, int n_in,
                              void* d_out, int out_size) {
    const float* feat = (const float*)d_in[0];
    const float* wgt  = (const float*)d_in[1];
    const float* bias = (const float*)d_in[2];
    const int*   nbr  = (const int*)d_in[3];
    float* out = (float*)d_out;

    cudaFuncSetAttribute(subm_conv_kernel,
                         cudaFuncAttributeMaxDynamicSharedMemorySize, SMEM_BYTES);
    subm_conv_kernel<<<148, NTHR, SMEM_BYTES>>>(feat, wgt, bias, nbr, out);
}